// round 10
// baseline (speedup 1.0000x reference)
#include <cuda_runtime.h>
#include <cuda_fp16.h>
#include <stdint.h>

#define NB 32
#define NC 8
#define NL 2048
#define NK 512
#define NS 64
#define NW (NL - NS + 1)   // 1985
#define MPAD 2048
#define KTOT 512           // NC * NS

// ---------------- device scratch (static, allocation-free) ----------------
__device__ __half g_A[(size_t)NB * MPAD * KTOT];   // 64 MB, [b][w][c*64+s]
__device__ __half g_B[(size_t)NK * KTOT];          // 512 KB, [k][c*64+s]

// ---------------- helpers ----------------
__device__ __forceinline__ uint32_t smem_u32(const void* p) {
    uint32_t a;
    asm("{ .reg .u64 t; cvta.to.shared.u64 t, %1; cvt.u32.u64 %0, t; }"
        : "=r"(a) : "l"(p));
    return a;
}

__device__ __forceinline__ void cp16(uint32_t dst, const void* src) {
    asm volatile("cp.async.cg.shared.global [%0], [%1], 16;" :: "r"(dst), "l"(src));
}

__device__ __forceinline__ void ldsm4(uint32_t* r, uint32_t addr) {
    asm volatile("ldmatrix.sync.aligned.m8n8.x4.shared.b16 {%0,%1,%2,%3}, [%4];"
                 : "=r"(r[0]), "=r"(r[1]), "=r"(r[2]), "=r"(r[3]) : "r"(addr));
}

// fp16-accumulate MMA: D(2 regs) = A(4) * B(2) + D
__device__ __forceinline__ void mma16816h(uint32_t* d, const uint32_t* a,
                                          const uint32_t* b) {
    asm volatile(
        "mma.sync.aligned.m16n8k16.row.col.f16.f16.f16.f16 "
        "{%0,%1}, {%2,%3,%4,%5}, {%6,%7}, {%0,%1};"
        : "+r"(d[0]), "+r"(d[1])
        : "r"(a[0]), "r"(a[1]), "r"(a[2]), "r"(a[3]), "r"(b[0]), "r"(b[1]));
}

// fp16-accumulate MMA with zero C (group init, no explicit acc zeroing)
__device__ __forceinline__ void mma16816h_z(uint32_t* d, const uint32_t* a,
                                            const uint32_t* b, uint32_t zz) {
    asm volatile(
        "mma.sync.aligned.m16n8k16.row.col.f16.f16.f16.f16 "
        "{%0,%1}, {%2,%3,%4,%5}, {%6,%7}, {%8,%8};"
        : "=r"(d[0]), "=r"(d[1])
        : "r"(a[0]), "r"(a[1]), "r"(a[2]), "r"(a[3]), "r"(b[0]), "r"(b[1]),
          "r"(zz));
}

// ---------------- Kernel 1: ONE-launch prep (+ output zeroing) -------------
// blocks [0,512):    B = fp16(sn_norm / 8), layout [k][c*64+s]
//   blocks [0,64) additionally zero the 16384-float output.
// blocks [512,4608): one (b, c, 128-w tile): window inv-norms from a
//                    192-float x slice, then A = fp16(x_window * inv).
__global__ __launch_bounds__(256) void prep_kernel(const float* __restrict__ x,
                                                   const float* __restrict__ sh,
                                                   float* __restrict__ out) {
    __shared__ float xs[192];
    __shared__ float invs[128];
    const int tid = threadIdx.x;
    if (blockIdx.x < 512) {
        if (blockIdx.x < 64) out[blockIdx.x * 256 + tid] = 0.f;
        int gw   = (blockIdx.x * 256 + tid) >> 5;
        int lane = tid & 31;
        int c = gw / NK, k = gw % NK;
        const float* row = sh + (size_t)(c * NK + k) * NS;
        float v0 = row[lane], v1 = row[lane + 32];
        float ss = v0 * v0 + v1 * v1;
        #pragma unroll
        for (int o = 16; o > 0; o >>= 1) ss += __shfl_xor_sync(0xffffffffu, ss, o);
        float sc = 0.125f / fmaxf(sqrtf(ss), 1e-8f);
        size_t base = (size_t)k * KTOT + c * 64 + lane;
        g_B[base]      = __float2half(v0 * sc);
        g_B[base + 32] = __float2half(v1 * sc);
        return;
    }
    const int id = blockIdx.x - 512;       // 0..4095
    const int wt = id & 15;
    const int c  = (id >> 4) & 7;
    const int b  = id >> 7;
    const int w0 = wt * 128;

    if (tid < 192) {
        int j = w0 + tid;
        xs[tid] = (j < NL) ? x[((size_t)(b * NC + c)) * NL + j] : 0.f;
    }
    __syncthreads();
    if (tid < 128) {
        int w = w0 + tid;
        if (w < NW) {
            float ss = 0.f;
            #pragma unroll 16
            for (int s = 0; s < NS; ++s) { float v = xs[tid + s]; ss += v * v; }
            invs[tid] = 1.0f / fmaxf(sqrtf(ss), 1e-8f);
        } else {
            invs[tid] = 0.f;
        }
    }
    __syncthreads();
    #pragma unroll
    for (int it = 0; it < 4; ++it) {
        int idx = it * 256 + tid;           // 1024 16B-chunks: 128 rows x 8
        int r = idx >> 3, s0 = (idx & 7) * 8;
        float inv = invs[r];
        __half h[8];
        #pragma unroll
        for (int j = 0; j < 8; ++j) h[j] = __float2half(xs[r + s0 + j] * inv);
        size_t base = ((size_t)(b * MPAD + w0 + r)) * KTOT + c * 64 + s0;
        *reinterpret_cast<uint4*>(&g_A[base]) = *reinterpret_cast<uint4*>(h);
    }
}

// ---------------- Kernel 2: fp16-acc mma GEMM + fp32 promotion -------------
// Block tile M=128 x N=128, 128 threads (4 warps, 2x2), warp tile 64x64.
// 2 CTAs/SM. K: 4 groups of 2 chunks (K=128/group); fp16 accumulate within
// a group (zero-C init), promote into fp32 shadow after each group.
#define NSTAGE 3
#define STAGE_BYTES 32768
#define OFF_B 16384
#define SMEM_BYTES (NSTAGE * STAGE_BYTES)   // 98304 per CTA

__global__ __launch_bounds__(128, 2) void gemm_kernel(float* __restrict__ out) {
    extern __shared__ char smem[];
    const uint32_t sb = smem_u32(smem);
    const int tid = threadIdx.x;
    const int wid = tid >> 5, lane = tid & 31;
    const int m0 = blockIdx.x * 128, n0 = blockIdx.y * 128, b = blockIdx.z;

    const int wm = wid & 1, wn = wid >> 1;   // 2 x 2 warp grid

    const int t8 = lane >> 3, lr = lane & 7;
    const int arow = wm * 64 + (t8 & 1) * 8 + lr;   // + i*16, i<4
    const int achk = t8 >> 1;                        // + 2*ks
    const int brow = wn * 64 + (t8 >> 1) * 8 + lr;  // + p*16, p<4
    const int bchk = t8 & 1;                         // + 2*ks
    const int arow7 = arow & 7, brow7 = brow & 7;
    const uint32_t aRowB0 = (uint32_t)(arow * 128);
    const uint32_t bRowB0 = (uint32_t)(brow * 128);

    const __half* A0 = g_A + ((size_t)(b * MPAD + m0)) * KTOT;
    const __half* B0 = g_B + (size_t)n0 * KTOT;

    // stage loader: A 128x64 (16 KB) + B 128x64 (16 KB), 16B-chunk XOR swizzle
    auto load_stage = [&](int cc, int s) {
        const uint32_t base = sb + s * STAGE_BYTES;
        const __half* ga = A0 + cc * 64;
        const __half* gb = B0 + cc * 64;
        #pragma unroll
        for (int j = 0; j < 8; ++j) {
            int i = j * 128 + tid;
            int row = i >> 3, c16 = i & 7;
            uint32_t so = (uint32_t)(row * 128 + ((c16 ^ (row & 7)) << 4));
            cp16(base + so, ga + (size_t)row * KTOT + c16 * 8);
        }
        #pragma unroll
        for (int j = 0; j < 8; ++j) {
            int i = j * 128 + tid;
            int row = i >> 3, c16 = i & 7;
            uint32_t so = (uint32_t)(row * 128 + ((c16 ^ (row & 7)) << 4));
            cp16(base + OFF_B + so, gb + (size_t)row * KTOT + c16 * 8);
        }
        asm volatile("cp.async.commit_group;");
    };

    float acc[4][8][4];              // fp32 shadow
    #pragma unroll
    for (int i = 0; i < 4; ++i)
        #pragma unroll
        for (int j = 0; j < 8; ++j)
            #pragma unroll
            for (int c = 0; c < 4; ++c) acc[i][j][c] = 0.f;

    uint32_t acc16[4][8][2];         // fp16x2 group accumulators
    const uint32_t zz = 0;

    load_stage(0, 0);
    load_stage(1, 1);

    for (int g = 0; g < 4; ++g) {
        #pragma unroll
        for (int h = 0; h < 2; ++h) {
            const int cc = 2 * g + h;
            if (cc < 7) asm volatile("cp.async.wait_group 1;");
            else        asm volatile("cp.async.wait_group 0;");
            __syncthreads();   // stage cc ready; overwritten stage free
            if (cc < 6) load_stage(cc + 2, (cc + 2) % NSTAGE);

            const uint32_t base = sb + (cc % NSTAGE) * STAGE_BYTES;
            const uint32_t aH = base, bH = base + OFF_B;

            #pragma unroll
            for (int ks = 0; ks < 4; ++ks) {
                uint32_t ah[4][4];
                const uint32_t axo = (uint32_t)(((achk + 2 * ks) ^ arow7) << 4);
                #pragma unroll
                for (int i = 0; i < 4; ++i)
                    ldsm4(ah[i], aH + aRowB0 + (uint32_t)(i * 16 * 128) + axo);
                uint32_t bh[4][4];
                const uint32_t bxo = (uint32_t)(((bchk + 2 * ks) ^ brow7) << 4);
                #pragma unroll
                for (int p = 0; p < 4; ++p)
                    ldsm4(bh[p], bH + bRowB0 + (uint32_t)(p * 16 * 128) + bxo);
                if (h == 0 && ks == 0) {
                    #pragma unroll
                    for (int p = 0; p < 4; ++p)
                        #pragma unroll
                        for (int i = 0; i < 4; ++i) {
                            mma16816h_z(acc16[i][2 * p],     ah[i], &bh[p][0], zz);
                            mma16816h_z(acc16[i][2 * p + 1], ah[i], &bh[p][2], zz);
                        }
                } else {
                    #pragma unroll
                    for (int p = 0; p < 4; ++p)
                        #pragma unroll
                        for (int i = 0; i < 4; ++i) {
                            mma16816h(acc16[i][2 * p],     ah[i], &bh[p][0]);
                            mma16816h(acc16[i][2 * p + 1], ah[i], &bh[p][2]);
                        }
                }
            }
        }
        // promote group sums into fp32 shadow (register-only; overlaps next
        // group's loads/MMAs after the barrier)
        #pragma unroll
        for (int i = 0; i < 4; ++i)
            #pragma unroll
            for (int j = 0; j < 8; ++j) {
                float2 u = __half22float2(
                    *reinterpret_cast<__half2*>(&acc16[i][j][0]));
                float2 v = __half22float2(
                    *reinterpret_cast<__half2*>(&acc16[i][j][1]));
                acc[i][j][0] += u.x; acc[i][j][1] += u.y;
                acc[i][j][2] += v.x; acc[i][j][3] += v.y;
            }
    }
    __syncthreads();   // protect smem reuse below

    // ---------------- epilogue: max over M (relu via 0-init) ---------------
    int* s_max = reinterpret_cast<int*>(smem);
    s_max[tid] = 0;
    __syncthreads();

    #pragma unroll
    for (int j = 0; j < 8; ++j) {
        float v0 = fmaxf(fmaxf(acc[0][j][0], acc[0][j][2]),
                         fmaxf(acc[1][j][0], acc[1][j][2]));
        v0 = fmaxf(v0, fmaxf(fmaxf(acc[2][j][0], acc[2][j][2]),
                             fmaxf(acc[3][j][0], acc[3][j][2])));
        float v1 = fmaxf(fmaxf(acc[0][j][1], acc[0][j][3]),
                         fmaxf(acc[1][j][1], acc[1][j][3]));
        v1 = fmaxf(v1, fmaxf(fmaxf(acc[2][j][1], acc[2][j][3]),
                             fmaxf(acc[3][j][1], acc[3][j][3])));
        #pragma unroll
        for (int off = 4; off < 32; off <<= 1) {
            v0 = fmaxf(v0, __shfl_xor_sync(0xffffffffu, v0, off));
            v1 = fmaxf(v1, __shfl_xor_sync(0xffffffffu, v1, off));
        }
        if (lane < 4) {
            int col = wn * 64 + j * 8 + lane * 2;
            atomicMax(&s_max[col],     __float_as_int(v0));
            atomicMax(&s_max[col + 1], __float_as_int(v1));
        }
    }
    __syncthreads();

    // all candidates >= 0 vs 0-init: signed-int max == relu'd float max
    atomicMax(reinterpret_cast<int*>(out + (size_t)b * NK + n0 + tid), s_max[tid]);
}

// ---------------- launch -----------------------------------------------------
extern "C" void kernel_launch(void* const* d_in, const int* in_sizes, int n_in,
                              void* d_out, int out_size) {
    const float* x  = (const float*)d_in[0];   // (B, C, L)
    const float* sh = (const float*)d_in[1];   // (C, K, S)
    float* out = (float*)d_out;                // (B, 1, K)

    prep_kernel<<<4608, 256>>>(x, sh, out);

    cudaFuncSetAttribute(gemm_kernel, cudaFuncAttributeMaxDynamicSharedMemorySize,
                         SMEM_BYTES);
    gemm_kernel<<<dim3(16, 4, 32), 128, SMEM_BYTES>>>(out);
}

// round 11
// speedup vs baseline: 1.0786x; 1.0786x over previous
#include <cuda_runtime.h>
#include <cuda_fp16.h>
#include <stdint.h>

#define NB 32
#define NC 8
#define NL 2048
#define NK 512
#define NS 64
#define NW (NL - NS + 1)   // 1985
#define MPAD 2048
#define KTOT 512           // NC * NS

// ---------------- device scratch (static, allocation-free) ----------------
__device__ __half g_A[(size_t)NB * MPAD * KTOT];   // 64 MB, [b][w][c*64+s]
__device__ __half g_B[(size_t)NK * KTOT];          // 512 KB, [k][c*64+s]

// ---------------- helpers ----------------
__device__ __forceinline__ uint32_t smem_u32(const void* p) {
    uint32_t a;
    asm("{ .reg .u64 t; cvta.to.shared.u64 t, %1; cvt.u32.u64 %0, t; }"
        : "=r"(a) : "l"(p));
    return a;
}

__device__ __forceinline__ void cp16(uint32_t dst, const void* src) {
    asm volatile("cp.async.cg.shared.global [%0], [%1], 16;" :: "r"(dst), "l"(src));
}

__device__ __forceinline__ void ldsm4(uint32_t* r, uint32_t addr) {
    asm volatile("ldmatrix.sync.aligned.m8n8.x4.shared.b16 {%0,%1,%2,%3}, [%4];"
                 : "=r"(r[0]), "=r"(r[1]), "=r"(r[2]), "=r"(r[3]) : "r"(addr));
}

__device__ __forceinline__ void mma16816(float* d, const uint32_t* a, const uint32_t* b) {
    asm volatile(
        "mma.sync.aligned.m16n8k16.row.col.f32.f16.f16.f32 "
        "{%0,%1,%2,%3}, {%4,%5,%6,%7}, {%8,%9}, {%0,%1,%2,%3};"
        : "+f"(d[0]), "+f"(d[1]), "+f"(d[2]), "+f"(d[3])
        : "r"(a[0]), "r"(a[1]), "r"(a[2]), "r"(a[3]), "r"(b[0]), "r"(b[1]));
}

// ---------------- Kernel 1: ONE-launch prep (+ output zeroing) -------------
// blocks [0,512):    B = fp16(sn_norm / 8), layout [k][c*64+s]
//   blocks [0,64) additionally zero the 16384-float output.
// blocks [512,4608): one (b, c, 128-w tile): window inv-norms from a
//                    192-float x slice, then A = fp16(x_window * inv).
__global__ __launch_bounds__(256) void prep_kernel(const float* __restrict__ x,
                                                   const float* __restrict__ sh,
                                                   float* __restrict__ out) {
    __shared__ float xs[192];
    __shared__ float invs[128];
    const int tid = threadIdx.x;
    if (blockIdx.x < 512) {
        if (blockIdx.x < 64) out[blockIdx.x * 256 + tid] = 0.f;
        int gw   = (blockIdx.x * 256 + tid) >> 5;
        int lane = tid & 31;
        int c = gw / NK, k = gw % NK;
        const float* row = sh + (size_t)(c * NK + k) * NS;
        float v0 = row[lane], v1 = row[lane + 32];
        float ss = v0 * v0 + v1 * v1;
        #pragma unroll
        for (int o = 16; o > 0; o >>= 1) ss += __shfl_xor_sync(0xffffffffu, ss, o);
        float sc = 0.125f / fmaxf(sqrtf(ss), 1e-8f);
        size_t base = (size_t)k * KTOT + c * 64 + lane;
        g_B[base]      = __float2half(v0 * sc);
        g_B[base + 32] = __float2half(v1 * sc);
        return;
    }
    const int id = blockIdx.x - 512;       // 0..4095
    const int wt = id & 15;
    const int c  = (id >> 4) & 7;
    const int b  = id >> 7;
    const int w0 = wt * 128;

    if (tid < 192) {
        int j = w0 + tid;
        xs[tid] = (j < NL) ? x[((size_t)(b * NC + c)) * NL + j] : 0.f;
    }
    __syncthreads();
    if (tid < 128) {
        int w = w0 + tid;
        if (w < NW) {
            float ss = 0.f;
            #pragma unroll 16
            for (int s = 0; s < NS; ++s) { float v = xs[tid + s]; ss += v * v; }
            invs[tid] = 1.0f / fmaxf(sqrtf(ss), 1e-8f);
        } else {
            invs[tid] = 0.f;
        }
    }
    __syncthreads();
    #pragma unroll
    for (int it = 0; it < 4; ++it) {
        int idx = it * 256 + tid;           // 1024 16B-chunks: 128 rows x 8
        int r = idx >> 3, s0 = (idx & 7) * 8;
        float inv = invs[r];
        __half h[8];
        #pragma unroll
        for (int j = 0; j < 8; ++j) h[j] = __float2half(xs[r + s0 + j] * inv);
        size_t base = ((size_t)(b * MPAD + w0 + r)) * KTOT + c * 64 + s0;
        *reinterpret_cast<uint4*>(&g_A[base]) = *reinterpret_cast<uint4*>(h);
    }
}

// ---------------- Kernel 2: fp32-acc mma GEMM, frag-pipelined --------------
// Block tile M=128 x N=128, 128 threads (4 warps, 2x2), warp tile 64x64.
// 2 CTAs/SM. K: 8 chunks of 64, 3-stage cp.async; A/B fragment registers
// double-buffered across ks-steps so ldsm(ks+1) overlaps MMAs(ks).
#define NSTAGE 3
#define STAGE_BYTES 32768
#define OFF_B 16384
#define SMEM_BYTES (NSTAGE * STAGE_BYTES)   // 98304 per CTA

__global__ __launch_bounds__(128, 2) void gemm_kernel(float* __restrict__ out) {
    extern __shared__ char smem[];
    const uint32_t sb = smem_u32(smem);
    const int tid = threadIdx.x;
    const int wid = tid >> 5, lane = tid & 31;
    const int m0 = blockIdx.x * 128, n0 = blockIdx.y * 128, b = blockIdx.z;

    const int wm = wid & 1, wn = wid >> 1;   // 2 x 2 warp grid

    const int t8 = lane >> 3, lr = lane & 7;
    const int arow = wm * 64 + (t8 & 1) * 8 + lr;   // + i*16, i<4
    const int achk = t8 >> 1;                        // + 2*ks
    const int brow = wn * 64 + (t8 >> 1) * 8 + lr;  // + p*16, p<4
    const int bchk = t8 & 1;                         // + 2*ks
    const int arow7 = arow & 7, brow7 = brow & 7;
    const uint32_t aRowB0 = (uint32_t)(arow * 128);
    const uint32_t bRowB0 = (uint32_t)(brow * 128);

    const __half* A0 = g_A + ((size_t)(b * MPAD + m0)) * KTOT;
    const __half* B0 = g_B + (size_t)n0 * KTOT;

    // stage loader: A 128x64 (16 KB) + B 128x64 (16 KB), 16B-chunk XOR swizzle
    auto load_stage = [&](int cc, int s) {
        const uint32_t base = sb + s * STAGE_BYTES;
        const __half* ga = A0 + cc * 64;
        const __half* gb = B0 + cc * 64;
        #pragma unroll
        for (int j = 0; j < 8; ++j) {
            int i = j * 128 + tid;
            int row = i >> 3, c16 = i & 7;
            uint32_t so = (uint32_t)(row * 128 + ((c16 ^ (row & 7)) << 4));
            cp16(base + so, ga + (size_t)row * KTOT + c16 * 8);
        }
        #pragma unroll
        for (int j = 0; j < 8; ++j) {
            int i = j * 128 + tid;
            int row = i >> 3, c16 = i & 7;
            uint32_t so = (uint32_t)(row * 128 + ((c16 ^ (row & 7)) << 4));
            cp16(base + OFF_B + so, gb + (size_t)row * KTOT + c16 * 8);
        }
        asm volatile("cp.async.commit_group;");
    };

    uint32_t ah[2][4][4], bh[2][4][4];   // double-buffered fragments

    // fragment loader for (stage base, ks) into buffer v
    auto ldfrags = [&](uint32_t base, int ks, int v) {
        const uint32_t aH = base, bH = base + OFF_B;
        const uint32_t axo = (uint32_t)(((achk + 2 * ks) ^ arow7) << 4);
        #pragma unroll
        for (int i = 0; i < 4; ++i)
            ldsm4(ah[v][i], aH + aRowB0 + (uint32_t)(i * 16 * 128) + axo);
        const uint32_t bxo = (uint32_t)(((bchk + 2 * ks) ^ brow7) << 4);
        #pragma unroll
        for (int p = 0; p < 4; ++p)
            ldsm4(bh[v][p], bH + bRowB0 + (uint32_t)(p * 16 * 128) + bxo);
    };

    float acc[4][8][4];
    #pragma unroll
    for (int i = 0; i < 4; ++i)
        #pragma unroll
        for (int j = 0; j < 8; ++j)
            #pragma unroll
            for (int c = 0; c < 4; ++c) acc[i][j][c] = 0.f;

    load_stage(0, 0);
    load_stage(1, 1);

    for (int cc = 0; cc < 8; ++cc) {
        if (cc < 7) asm volatile("cp.async.wait_group 1;");
        else        asm volatile("cp.async.wait_group 0;");
        __syncthreads();   // stage cc visible to all; overwritten stage free
        if (cc < 6) load_stage(cc + 2, (cc + 2) % NSTAGE);

        const uint32_t base = sb + (cc % NSTAGE) * STAGE_BYTES;
        ldfrags(base, 0, 0);                 // exposed once per chunk

        #pragma unroll
        for (int ks = 0; ks < 4; ++ks) {
            const int cur = ks & 1;
            if (ks < 3) ldfrags(base, ks + 1, cur ^ 1);   // overlap with MMAs
            #pragma unroll
            for (int p = 0; p < 4; ++p) {
                #pragma unroll
                for (int i = 0; i < 4; ++i) {
                    mma16816(acc[i][2 * p],     ah[cur][i], &bh[cur][p][0]);
                    mma16816(acc[i][2 * p + 1], ah[cur][i], &bh[cur][p][2]);
                }
            }
        }
    }
    __syncthreads();   // protect smem reuse below

    // ---------------- epilogue: max over M (relu via 0-init) ---------------
    int* s_max = reinterpret_cast<int*>(smem);
    s_max[tid] = 0;
    __syncthreads();

    #pragma unroll
    for (int j = 0; j < 8; ++j) {
        float v0 = fmaxf(fmaxf(acc[0][j][0], acc[0][j][2]),
                         fmaxf(acc[1][j][0], acc[1][j][2]));
        v0 = fmaxf(v0, fmaxf(fmaxf(acc[2][j][0], acc[2][j][2]),
                             fmaxf(acc[3][j][0], acc[3][j][2])));
        float v1 = fmaxf(fmaxf(acc[0][j][1], acc[0][j][3]),
                         fmaxf(acc[1][j][1], acc[1][j][3]));
        v1 = fmaxf(v1, fmaxf(fmaxf(acc[2][j][1], acc[2][j][3]),
                             fmaxf(acc[3][j][1], acc[3][j][3])));
        #pragma unroll
        for (int off = 4; off < 32; off <<= 1) {
            v0 = fmaxf(v0, __shfl_xor_sync(0xffffffffu, v0, off));
            v1 = fmaxf(v1, __shfl_xor_sync(0xffffffffu, v1, off));
        }
        if (lane < 4) {
            int col = wn * 64 + j * 8 + lane * 2;
            atomicMax(&s_max[col],     __float_as_int(v0));
            atomicMax(&s_max[col + 1], __float_as_int(v1));
        }
    }
    __syncthreads();

    // all candidates >= 0 vs 0-init: signed-int max == relu'd float max
    atomicMax(reinterpret_cast<int*>(out + (size_t)b * NK + n0 + tid), s_max[tid]);
}

// ---------------- launch -----------------------------------------------------
extern "C" void kernel_launch(void* const* d_in, const int* in_sizes, int n_in,
                              void* d_out, int out_size) {
    const float* x  = (const float*)d_in[0];   // (B, C, L)
    const float* sh = (const float*)d_in[1];   // (C, K, S)
    float* out = (float*)d_out;                // (B, 1, K)

    prep_kernel<<<4608, 256>>>(x, sh, out);

    cudaFuncSetAttribute(gemm_kernel, cudaFuncAttributeMaxDynamicSharedMemorySize,
                         SMEM_BYTES);
    gemm_kernel<<<dim3(16, 4, 32), 128, SMEM_BYTES>>>(out);
}

// round 12
// speedup vs baseline: 1.1254x; 1.0433x over previous
#include <cuda_runtime.h>
#include <cuda_fp16.h>
#include <stdint.h>

#define NB 32
#define NC 8
#define NL 2048
#define NK 512
#define NS 64
#define NW (NL - NS + 1)   // 1985
#define MPAD 2048
#define KTOT 512           // NC * NS

// ---------------- device scratch (static, allocation-free) ----------------
__device__ __half g_A[(size_t)NB * MPAD * KTOT];   // 64 MB, [b][w][c*64+s]
__device__ __half g_B[(size_t)NK * KTOT];          // 512 KB, [k][c*64+s]

// ---------------- helpers ----------------
__device__ __forceinline__ uint32_t smem_u32(const void* p) {
    uint32_t a;
    asm("{ .reg .u64 t; cvta.to.shared.u64 t, %1; cvt.u32.u64 %0, t; }"
        : "=r"(a) : "l"(p));
    return a;
}

__device__ __forceinline__ void cp16(uint32_t dst, const void* src) {
    asm volatile("cp.async.cg.shared.global [%0], [%1], 16;" :: "r"(dst), "l"(src));
}

__device__ __forceinline__ void ldsm4(uint32_t* r, uint32_t addr) {
    asm volatile("ldmatrix.sync.aligned.m8n8.x4.shared.b16 {%0,%1,%2,%3}, [%4];"
                 : "=r"(r[0]), "=r"(r[1]), "=r"(r[2]), "=r"(r[3]) : "r"(addr));
}

__device__ __forceinline__ void mma16816(float* d, const uint32_t* a, const uint32_t* b) {
    asm volatile(
        "mma.sync.aligned.m16n8k16.row.col.f32.f16.f16.f32 "
        "{%0,%1,%2,%3}, {%4,%5,%6,%7}, {%8,%9}, {%0,%1,%2,%3};"
        : "+f"(d[0]), "+f"(d[1]), "+f"(d[2]), "+f"(d[3])
        : "r"(a[0]), "r"(a[1]), "r"(a[2]), "r"(a[3]), "r"(b[0]), "r"(b[1]));
}

// ---------------- Kernel 1: ONE-launch prep (+ output zeroing) -------------
// blocks [0,512):    B = fp16(sn_norm / 8), layout [k][c*64+s]
//   blocks [0,64) additionally zero the 16384-float output.
// blocks [512,4608): one (b, c, 128-w tile): window inv-norms from a
//                    192-float x slice, then A = fp16(x_window * inv).
__global__ __launch_bounds__(256) void prep_kernel(const float* __restrict__ x,
                                                   const float* __restrict__ sh,
                                                   float* __restrict__ out) {
    __shared__ float xs[192];
    __shared__ float invs[128];
    const int tid = threadIdx.x;
    if (blockIdx.x < 512) {
        if (blockIdx.x < 64) out[blockIdx.x * 256 + tid] = 0.f;
        int gw   = (blockIdx.x * 256 + tid) >> 5;
        int lane = tid & 31;
        int c = gw / NK, k = gw % NK;
        const float* row = sh + (size_t)(c * NK + k) * NS;
        float v0 = row[lane], v1 = row[lane + 32];
        float ss = v0 * v0 + v1 * v1;
        #pragma unroll
        for (int o = 16; o > 0; o >>= 1) ss += __shfl_xor_sync(0xffffffffu, ss, o);
        float sc = 0.125f / fmaxf(sqrtf(ss), 1e-8f);
        size_t base = (size_t)k * KTOT + c * 64 + lane;
        g_B[base]      = __float2half(v0 * sc);
        g_B[base + 32] = __float2half(v1 * sc);
        return;
    }
    const int id = blockIdx.x - 512;       // 0..4095
    const int wt = id & 15;
    const int c  = (id >> 4) & 7;
    const int b  = id >> 7;
    const int w0 = wt * 128;

    if (tid < 192) {
        int j = w0 + tid;
        xs[tid] = (j < NL) ? x[((size_t)(b * NC + c)) * NL + j] : 0.f;
    }
    __syncthreads();
    if (tid < 128) {
        int w = w0 + tid;
        if (w < NW) {
            float ss = 0.f;
            #pragma unroll 16
            for (int s = 0; s < NS; ++s) { float v = xs[tid + s]; ss += v * v; }
            invs[tid] = 1.0f / fmaxf(sqrtf(ss), 1e-8f);
        } else {
            invs[tid] = 0.f;
        }
    }
    __syncthreads();
    #pragma unroll
    for (int it = 0; it < 4; ++it) {
        int idx = it * 256 + tid;           // 1024 16B-chunks: 128 rows x 8
        int r = idx >> 3, s0 = (idx & 7) * 8;
        float inv = invs[r];
        __half h[8];
        #pragma unroll
        for (int j = 0; j < 8; ++j) h[j] = __float2half(xs[r + s0 + j] * inv);
        size_t base = ((size_t)(b * MPAD + w0 + r)) * KTOT + c * 64 + s0;
        *reinterpret_cast<uint4*>(&g_A[base]) = *reinterpret_cast<uint4*>(h);
    }
}

// ---------------- Kernel 2: fp32-acc mma GEMM, spread prefetch -------------
// Block tile M=128 x N=128, 128 threads (4 warps, 2x2), warp tile 64x64.
// 2 CTAs/SM. K: 8 chunks of 64, 3-stage cp.async. Fragments for ks=0 load
// immediately after the barrier; stage-(cc+2) cp.asyncs issued in quarters
// between ks-iterations so the chunk head has no load burst.
#define NSTAGE 3
#define STAGE_BYTES 32768
#define OFF_B 16384
#define SMEM_BYTES (NSTAGE * STAGE_BYTES)   // 98304 per CTA

__global__ __launch_bounds__(128, 2) void gemm_kernel(float* __restrict__ out) {
    extern __shared__ char smem[];
    const uint32_t sb = smem_u32(smem);
    const int tid = threadIdx.x;
    const int wid = tid >> 5, lane = tid & 31;
    const int m0 = blockIdx.x * 128, n0 = blockIdx.y * 128, b = blockIdx.z;

    const int wm = wid & 1, wn = wid >> 1;   // 2 x 2 warp grid

    const int t8 = lane >> 3, lr = lane & 7;
    const int arow = wm * 64 + (t8 & 1) * 8 + lr;   // + i*16, i<4
    const int achk = t8 >> 1;                        // + 2*ks
    const int brow = wn * 64 + (t8 >> 1) * 8 + lr;  // + p*16, p<4
    const int bchk = t8 & 1;                         // + 2*ks
    const int arow7 = arow & 7, brow7 = brow & 7;
    const uint32_t aRowB0 = (uint32_t)(arow * 128);
    const uint32_t bRowB0 = (uint32_t)(brow * 128);

    const __half* A0 = g_A + ((size_t)(b * MPAD + m0)) * KTOT;
    const __half* B0 = g_B + (size_t)n0 * KTOT;

    // quarter stage loader: q in [0,4); j = 2q, 2q+1 of 8 row-groups for A & B
    auto load_stage_q = [&](int cc, int s, int q) {
        const uint32_t base = sb + s * STAGE_BYTES;
        const __half* ga = A0 + cc * 64;
        const __half* gb = B0 + cc * 64;
        #pragma unroll
        for (int j = 2 * q; j < 2 * q + 2; ++j) {
            int i = j * 128 + tid;
            int row = i >> 3, c16 = i & 7;
            uint32_t so = (uint32_t)(row * 128 + ((c16 ^ (row & 7)) << 4));
            cp16(base + so, ga + (size_t)row * KTOT + c16 * 8);
            cp16(base + OFF_B + so, gb + (size_t)row * KTOT + c16 * 8);
        }
    };
    auto load_stage = [&](int cc, int s) {
        #pragma unroll
        for (int q = 0; q < 4; ++q) load_stage_q(cc, s, q);
        asm volatile("cp.async.commit_group;");
    };

    uint32_t ah[2][4][4], bh[2][4][4];   // double-buffered fragments

    auto ldfrags = [&](uint32_t base, int ks, int v) {
        const uint32_t aH = base, bH = base + OFF_B;
        const uint32_t axo = (uint32_t)(((achk + 2 * ks) ^ arow7) << 4);
        #pragma unroll
        for (int i = 0; i < 4; ++i)
            ldsm4(ah[v][i], aH + aRowB0 + (uint32_t)(i * 16 * 128) + axo);
        const uint32_t bxo = (uint32_t)(((bchk + 2 * ks) ^ brow7) << 4);
        #pragma unroll
        for (int p = 0; p < 4; ++p)
            ldsm4(bh[v][p], bH + bRowB0 + (uint32_t)(p * 16 * 128) + bxo);
    };

    float acc[4][8][4];
    #pragma unroll
    for (int i = 0; i < 4; ++i)
        #pragma unroll
        for (int j = 0; j < 8; ++j)
            #pragma unroll
            for (int c = 0; c < 4; ++c) acc[i][j][c] = 0.f;

    load_stage(0, 0);
    load_stage(1, 1);

    for (int cc = 0; cc < 8; ++cc) {
        if (cc < 7) asm volatile("cp.async.wait_group 1;");
        else        asm volatile("cp.async.wait_group 0;");
        __syncthreads();   // stage cc visible; overwritten stage free

        const uint32_t base = sb + (cc % NSTAGE) * STAGE_BYTES;
        ldfrags(base, 0, 0);             // fragments first — MMAs start ASAP

        const bool pf = (cc < 6);
        const int  ps = (cc + 2) % NSTAGE;

        #pragma unroll
        for (int ks = 0; ks < 4; ++ks) {
            const int cur = ks & 1;
            if (ks < 3) ldfrags(base, ks + 1, cur ^ 1);
            if (pf) load_stage_q(cc + 2, ps, ks);   // spread prefetch
            #pragma unroll
            for (int p = 0; p < 4; ++p) {
                #pragma unroll
                for (int i = 0; i < 4; ++i) {
                    mma16816(acc[i][2 * p],     ah[cur][i], &bh[cur][p][0]);
                    mma16816(acc[i][2 * p + 1], ah[cur][i], &bh[cur][p][2]);
                }
            }
        }
        if (pf) asm volatile("cp.async.commit_group;");
    }
    __syncthreads();   // protect smem reuse below

    // ---------------- epilogue: max over M (relu via 0-init) ---------------
    int* s_max = reinterpret_cast<int*>(smem);
    s_max[tid] = 0;
    __syncthreads();

    #pragma unroll
    for (int j = 0; j < 8; ++j) {
        float v0 = fmaxf(fmaxf(acc[0][j][0], acc[0][j][2]),
                         fmaxf(acc[1][j][0], acc[1][j][2]));
        v0 = fmaxf(v0, fmaxf(fmaxf(acc[2][j][0], acc[2][j][2]),
                             fmaxf(acc[3][j][0], acc[3][j][2])));
        float v1 = fmaxf(fmaxf(acc[0][j][1], acc[0][j][3]),
                         fmaxf(acc[1][j][1], acc[1][j][3]));
        v1 = fmaxf(v1, fmaxf(fmaxf(acc[2][j][1], acc[2][j][3]),
                             fmaxf(acc[3][j][1], acc[3][j][3])));
        #pragma unroll
        for (int off = 4; off < 32; off <<= 1) {
            v0 = fmaxf(v0, __shfl_xor_sync(0xffffffffu, v0, off));
            v1 = fmaxf(v1, __shfl_xor_sync(0xffffffffu, v1, off));
        }
        if (lane < 4) {
            int col = wn * 64 + j * 8 + lane * 2;
            atomicMax(&s_max[col],     __float_as_int(v0));
            atomicMax(&s_max[col + 1], __float_as_int(v1));
        }
    }
    __syncthreads();

    // all candidates >= 0 vs 0-init: signed-int max == relu'd float max
    atomicMax(reinterpret_cast<int*>(out + (size_t)b * NK + n0 + tid), s_max[tid]);
}

// ---------------- launch -----------------------------------------------------
extern "C" void kernel_launch(void* const* d_in, const int* in_sizes, int n_in,
                              void* d_out, int out_size) {
    const float* x  = (const float*)d_in[0];   // (B, C, L)
    const float* sh = (const float*)d_in[1];   // (C, K, S)
    float* out = (float*)d_out;                // (B, 1, K)

    prep_kernel<<<4608, 256>>>(x, sh, out);

    cudaFuncSetAttribute(gemm_kernel, cudaFuncAttributeMaxDynamicSharedMemorySize,
                         SMEM_BYTES);
    gemm_kernel<<<dim3(16, 4, 32), 128, SMEM_BYTES>>>(out);
}

// round 13
// speedup vs baseline: 1.1759x; 1.0449x over previous
#include <cuda_runtime.h>
#include <cuda_fp16.h>
#include <stdint.h>

#define NB 32
#define NC 8
#define NL 2048
#define NK 512
#define NS 64
#define NW (NL - NS + 1)   // 1985
#define KTOT 512           // NC * NS

// ---------------- device scratch: pre-swizzled contiguous tile blobs -------
// A blob: (b, mtile 0..15, chunk 0..7) -> 16 KB smem image (128 rows x 128 B,
// 16B-chunk XOR swizzle). B blob: (ntile 0..3, chunk 0..7) -> 16 KB image.
__device__ __align__(128) __half g_Asw[(size_t)NB * 16 * 8 * 8192];  // 64 MB
__device__ __align__(128) __half g_Bsw[(size_t)4 * 8 * 8192];        // 512 KB

// ---------------- helpers ----------------
__device__ __forceinline__ uint32_t smem_u32(const void* p) {
    uint32_t a;
    asm("{ .reg .u64 t; cvta.to.shared.u64 t, %1; cvt.u32.u64 %0, t; }"
        : "=r"(a) : "l"(p));
    return a;
}

__device__ __forceinline__ void ldsm4(uint32_t* r, uint32_t addr) {
    asm volatile("ldmatrix.sync.aligned.m8n8.x4.shared.b16 {%0,%1,%2,%3}, [%4];"
                 : "=r"(r[0]), "=r"(r[1]), "=r"(r[2]), "=r"(r[3]) : "r"(addr));
}

__device__ __forceinline__ void mma16816(float* d, const uint32_t* a, const uint32_t* b) {
    asm volatile(
        "mma.sync.aligned.m16n8k16.row.col.f32.f16.f16.f32 "
        "{%0,%1,%2,%3}, {%4,%5,%6,%7}, {%8,%9}, {%0,%1,%2,%3};"
        : "+f"(d[0]), "+f"(d[1]), "+f"(d[2]), "+f"(d[3])
        : "r"(a[0]), "r"(a[1]), "r"(a[2]), "r"(a[3]), "r"(b[0]), "r"(b[1]));
}

__device__ __forceinline__ void mbar_init(uint32_t mbar, uint32_t cnt) {
    asm volatile("mbarrier.init.shared.b64 [%0], %1;" :: "r"(mbar), "r"(cnt) : "memory");
}
__device__ __forceinline__ void mbar_arrive(uint32_t mbar) {
    asm volatile("mbarrier.arrive.shared.b64 _, [%0];" :: "r"(mbar) : "memory");
}
__device__ __forceinline__ void mbar_expect_tx(uint32_t mbar, uint32_t tx) {
    asm volatile("mbarrier.arrive.expect_tx.shared.b64 _, [%0], %1;"
                 :: "r"(mbar), "r"(tx) : "memory");
}
__device__ __forceinline__ void mbar_wait(uint32_t mbar, uint32_t parity) {
    asm volatile(
        "{\n\t"
        ".reg .pred P;\n\t"
        "WAITLOOP_%=:\n\t"
        "mbarrier.try_wait.parity.acquire.cta.shared::cta.b64 P, [%0], %1, 0x989680;\n\t"
        "@P bra.uni WAITDONE_%=;\n\t"
        "bra.uni WAITLOOP_%=;\n\t"
        "WAITDONE_%=:\n\t"
        "}" :: "r"(mbar), "r"(parity) : "memory");
}
__device__ __forceinline__ void bulk_cp(uint32_t dst, const void* src,
                                        uint32_t bytes, uint32_t mbar) {
    asm volatile(
        "cp.async.bulk.shared::cluster.global.mbarrier::complete_tx::bytes "
        "[%0], [%1], %2, [%3];"
        :: "r"(dst), "l"(src), "r"(bytes), "r"(mbar) : "memory");
}

// ---------------- Kernel 1: ONE-launch prep (pre-swizzled blobs) -----------
// blocks [0,512):    B blobs = fp16(sn_norm / 8); blocks [0,64) zero output.
// blocks [512,4608): one (b, c, 128-w tile): window inv-norms from a
//                    192-float x slice, then A blob = fp16(x_window * inv).
__global__ __launch_bounds__(256) void prep_kernel(const float* __restrict__ x,
                                                   const float* __restrict__ sh,
                                                   float* __restrict__ out) {
    __shared__ float xs[192];
    __shared__ float invs[128];
    const int tid = threadIdx.x;
    if (blockIdx.x < 512) {
        if (blockIdx.x < 64) out[blockIdx.x * 256 + tid] = 0.f;
        int gw   = (blockIdx.x * 256 + tid) >> 5;
        int lane = tid & 31;
        int c = gw / NK, k = gw % NK;
        const float* row = sh + (size_t)(c * NK + k) * NS;
        float v0 = row[lane], v1 = row[lane + 32];
        float ss = v0 * v0 + v1 * v1;
        #pragma unroll
        for (int o = 16; o > 0; o >>= 1) ss += __shfl_xor_sync(0xffffffffu, ss, o);
        float sc = 0.125f / fmaxf(sqrtf(ss), 1e-8f);
        // B blob layout: ntile = k>>7, row r = k&127, chunk = c
        char* blob = (char*)g_Bsw + ((((size_t)(k >> 7)) * 8 + c) << 14);
        int r = k & 127;
        #pragma unroll
        for (int h = 0; h < 2; ++h) {
            int s = lane + 32 * h;
            int c16 = s >> 3, inner = s & 7;
            uint32_t off = (uint32_t)(r * 128 + ((c16 ^ (r & 7)) << 4) + inner * 2);
            *reinterpret_cast<__half*>(blob + off) = __float2half(h ? v1 * sc : v0 * sc);
        }
        return;
    }
    const int id = blockIdx.x - 512;       // 0..4095
    const int wt = id & 15;
    const int c  = (id >> 4) & 7;
    const int b  = id >> 7;
    const int w0 = wt * 128;

    if (tid < 192) {
        int j = w0 + tid;
        xs[tid] = (j < NL) ? x[((size_t)(b * NC + c)) * NL + j] : 0.f;
    }
    __syncthreads();
    if (tid < 128) {
        int w = w0 + tid;
        if (w < NW) {
            float ss = 0.f;
            #pragma unroll 16
            for (int s = 0; s < NS; ++s) { float v = xs[tid + s]; ss += v * v; }
            invs[tid] = 1.0f / fmaxf(sqrtf(ss), 1e-8f);
        } else {
            invs[tid] = 0.f;
        }
    }
    __syncthreads();
    char* blob = (char*)g_Asw + ((((size_t)(b * 16 + wt)) * 8 + c) << 14);
    #pragma unroll
    for (int it = 0; it < 4; ++it) {
        int idx = it * 256 + tid;           // 1024 16B-chunks: 128 rows x 8
        int r = idx >> 3, c16 = idx & 7;
        float inv = invs[r];
        __half h[8];
        #pragma unroll
        for (int j = 0; j < 8; ++j) h[j] = __float2half(xs[r + c16 * 8 + j] * inv);
        uint32_t so = (uint32_t)(r * 128 + ((c16 ^ (r & 7)) << 4));
        *reinterpret_cast<uint4*>(blob + so) = *reinterpret_cast<uint4*>(h);
    }
}

// ---------------- Kernel 2: async-pipelined fp32-acc mma GEMM --------------
// Block tile M=128 x N=128, 128 threads (4 warps, 2x2), warp tile 64x64.
// 2 CTAs/SM. 8 K-chunks, 3 stages; cp.async.bulk blob copies signalled by
// mbarrier complete_tx. NO __syncthreads in the mainloop: consumers wait
// full[slot] (acquire), each warp arrives empty[slot] when done reading.
#define NSTAGE 3
#define STAGE_BYTES 32768
#define OFF_B 16384
#define MBAR_OFF (NSTAGE * STAGE_BYTES)          // 98304
#define SMEM_BYTES (MBAR_OFF + 64)               // 98368 per CTA

__global__ __launch_bounds__(128, 2) void gemm_kernel(float* __restrict__ out) {
    extern __shared__ char smem[];
    const uint32_t sb = smem_u32(smem);
    const int tid = threadIdx.x;
    const int wid = tid >> 5, lane = tid & 31;
    const int n0 = blockIdx.y * 128, b = blockIdx.z;

    const int wm = wid & 1, wn = wid >> 1;   // 2 x 2 warp grid

    const int t8 = lane >> 3, lr = lane & 7;
    const int arow = wm * 64 + (t8 & 1) * 8 + lr;   // + i*16, i<4
    const int achk = t8 >> 1;                        // + 2*ks
    const int brow = wn * 64 + (t8 >> 1) * 8 + lr;  // + p*16, p<4
    const int bchk = t8 & 1;                         // + 2*ks
    const int arow7 = arow & 7, brow7 = brow & 7;
    const uint32_t aRowB0 = (uint32_t)(arow * 128);
    const uint32_t bRowB0 = (uint32_t)(brow * 128);

    const char* Ablob0 = (const char*)g_Asw +
                         (((size_t)(b * 16 + blockIdx.x)) * 8 << 14);
    const char* Bblob0 = (const char*)g_Bsw + ((size_t)blockIdx.y * 8 << 14);

    const uint32_t mb_full0  = sb + MBAR_OFF;        // +8 per slot
    const uint32_t mb_empty0 = sb + MBAR_OFF + 24;   // +8 per slot

    if (tid == 0) {
        #pragma unroll
        for (int s = 0; s < NSTAGE; ++s) {
            mbar_init(mb_full0 + s * 8, 1);    // tx-based completion
            mbar_init(mb_empty0 + s * 8, 4);   // one arrive per warp
        }
    }
    __syncthreads();

    // producer cursor (tid 0 only): phase starts 1 so first waits pass
    int prod_slot = 0, prod_ph = 1;
    auto issue = [&](int cc) {
        const uint32_t fullb = mb_full0 + prod_slot * 8;
        mbar_wait(mb_empty0 + prod_slot * 8, (uint32_t)prod_ph);
        mbar_expect_tx(fullb, 2 * 16384u);
        const uint32_t dst = sb + prod_slot * STAGE_BYTES;
        bulk_cp(dst,         Ablob0 + ((size_t)cc << 14), 16384u, fullb);
        bulk_cp(dst + OFF_B, Bblob0 + ((size_t)cc << 14), 16384u, fullb);
        if (++prod_slot == NSTAGE) { prod_slot = 0; prod_ph ^= 1; }
    };

    uint32_t ah[2][4][4], bh[2][4][4];   // double-buffered fragments
    auto ldfrags = [&](uint32_t base, int ks, int v) {
        const uint32_t aH = base, bH = base + OFF_B;
        const uint32_t axo = (uint32_t)(((achk + 2 * ks) ^ arow7) << 4);
        #pragma unroll
        for (int i = 0; i < 4; ++i)
            ldsm4(ah[v][i], aH + aRowB0 + (uint32_t)(i * 16 * 128) + axo);
        const uint32_t bxo = (uint32_t)(((bchk + 2 * ks) ^ brow7) << 4);
        #pragma unroll
        for (int p = 0; p < 4; ++p)
            ldsm4(bh[v][p], bH + bRowB0 + (uint32_t)(p * 16 * 128) + bxo);
    };

    float acc[4][8][4];
    #pragma unroll
    for (int i = 0; i < 4; ++i)
        #pragma unroll
        for (int j = 0; j < 8; ++j)
            #pragma unroll
            for (int c = 0; c < 4; ++c) acc[i][j][c] = 0.f;

    if (tid == 0) { issue(0); issue(1); }

    // consumer cursor (all threads): phase starts 0
    int cons_slot = 0, cons_ph = 0;

    for (int cc = 0; cc < 8; ++cc) {
        if (tid == 0 && cc < 6) issue(cc + 2);

        mbar_wait(mb_full0 + cons_slot * 8, (uint32_t)cons_ph);
        const uint32_t base = sb + cons_slot * STAGE_BYTES;
        ldfrags(base, 0, 0);

        #pragma unroll
        for (int ks = 0; ks < 4; ++ks) {
            const int cur = ks & 1;
            if (ks < 3) ldfrags(base, ks + 1, cur ^ 1);
            #pragma unroll
            for (int p = 0; p < 4; ++p) {
                #pragma unroll
                for (int i = 0; i < 4; ++i) {
                    mma16816(acc[i][2 * p],     ah[cur][i], &bh[cur][p][0]);
                    mma16816(acc[i][2 * p + 1], ah[cur][i], &bh[cur][p][2]);
                }
            }
        }
        if (lane == 0) mbar_arrive(mb_empty0 + cons_slot * 8);
        if (++cons_slot == NSTAGE) { cons_slot = 0; cons_ph ^= 1; }
    }
    __syncthreads();   // all copies consumed; safe to reuse smem

    // ---------------- epilogue: max over M (relu via 0-init) ---------------
    int* s_max = reinterpret_cast<int*>(smem);
    s_max[tid] = 0;
    __syncthreads();

    #pragma unroll
    for (int j = 0; j < 8; ++j) {
        float v0 = fmaxf(fmaxf(acc[0][j][0], acc[0][j][2]),
                         fmaxf(acc[1][j][0], acc[1][j][2]));
        v0 = fmaxf(v0, fmaxf(fmaxf(acc[2][j][0], acc[2][j][2]),
                             fmaxf(acc[3][j][0], acc[3][j][2])));
        float v1 = fmaxf(fmaxf(acc[0][j][1], acc[0][j][3]),
                         fmaxf(acc[1][j][1], acc[1][j][3]));
        v1 = fmaxf(v1, fmaxf(fmaxf(acc[2][j][1], acc[2][j][3]),
                             fmaxf(acc[3][j][1], acc[3][j][3])));
        #pragma unroll
        for (int off = 4; off < 32; off <<= 1) {
            v0 = fmaxf(v0, __shfl_xor_sync(0xffffffffu, v0, off));
            v1 = fmaxf(v1, __shfl_xor_sync(0xffffffffu, v1, off));
        }
        if (lane < 4) {
            int col = wn * 64 + j * 8 + lane * 2;
            atomicMax(&s_max[col],     __float_as_int(v0));
            atomicMax(&s_max[col + 1], __float_as_int(v1));
        }
    }
    __syncthreads();

    // all candidates >= 0 vs 0-init: signed-int max == relu'd float max
    atomicMax(reinterpret_cast<int*>(out + (size_t)b * NK + n0 + tid), s_max[tid]);
}

// ---------------- launch -----------------------------------------------------
extern "C" void kernel_launch(void* const* d_in, const int* in_sizes, int n_in,
                              void* d_out, int out_size) {
    const float* x  = (const float*)d_in[0];   // (B, C, L)
    const float* sh = (const float*)d_in[1];   // (C, K, S)
    float* out = (float*)d_out;                // (B, 1, K)

    prep_kernel<<<4608, 256>>>(x, sh, out);

    cudaFuncSetAttribute(gemm_kernel, cudaFuncAttributeMaxDynamicSharedMemorySize,
                         SMEM_BYTES);
    gemm_kernel<<<dim3(16, 4, 32), 128, SMEM_BYTES>>>(out);
}

// round 14
// speedup vs baseline: 1.1833x; 1.0063x over previous
#include <cuda_runtime.h>
#include <cuda_fp16.h>
#include <stdint.h>

#define NB 32
#define NC 8
#define NL 2048
#define NK 512
#define NS 64
#define NW (NL - NS + 1)   // 1985
#define KTOT 512           // NC * NS

// ---------------- device scratch: pre-swizzled contiguous tile blobs -------
// A blob: (b, mtile 0..15, chunk 0..7) -> 16 KB smem image (128 rows x 128 B,
// 16B-chunk XOR swizzle). B blob: (ntile 0..3, chunk 0..7) -> 16 KB image.
__device__ __align__(128) __half g_Asw[(size_t)NB * 16 * 8 * 8192];  // 64 MB
__device__ __align__(128) __half g_Bsw[(size_t)4 * 8 * 8192];        // 512 KB

// ---------------- helpers ----------------
__device__ __forceinline__ uint32_t smem_u32(const void* p) {
    uint32_t a;
    asm("{ .reg .u64 t; cvta.to.shared.u64 t, %1; cvt.u32.u64 %0, t; }"
        : "=r"(a) : "l"(p));
    return a;
}

__device__ __forceinline__ void ldsm4(uint32_t* r, uint32_t addr) {
    asm volatile("ldmatrix.sync.aligned.m8n8.x4.shared.b16 {%0,%1,%2,%3}, [%4];"
                 : "=r"(r[0]), "=r"(r[1]), "=r"(r[2]), "=r"(r[3]) : "r"(addr));
}

__device__ __forceinline__ void mma16816(float* d, const uint32_t* a, const uint32_t* b) {
    asm volatile(
        "mma.sync.aligned.m16n8k16.row.col.f32.f16.f16.f32 "
        "{%0,%1,%2,%3}, {%4,%5,%6,%7}, {%8,%9}, {%0,%1,%2,%3};"
        : "+f"(d[0]), "+f"(d[1]), "+f"(d[2]), "+f"(d[3])
        : "r"(a[0]), "r"(a[1]), "r"(a[2]), "r"(a[3]), "r"(b[0]), "r"(b[1]));
}

__device__ __forceinline__ void mbar_init(uint32_t mbar, uint32_t cnt) {
    asm volatile("mbarrier.init.shared.b64 [%0], %1;" :: "r"(mbar), "r"(cnt) : "memory");
}
__device__ __forceinline__ void mbar_arrive(uint32_t mbar) {
    asm volatile("mbarrier.arrive.shared.b64 _, [%0];" :: "r"(mbar) : "memory");
}
__device__ __forceinline__ void mbar_expect_tx(uint32_t mbar, uint32_t tx) {
    asm volatile("mbarrier.arrive.expect_tx.shared.b64 _, [%0], %1;"
                 :: "r"(mbar), "r"(tx) : "memory");
}
__device__ __forceinline__ void mbar_wait(uint32_t mbar, uint32_t parity) {
    asm volatile(
        "{\n\t"
        ".reg .pred P;\n\t"
        "WAITLOOP_%=:\n\t"
        "mbarrier.try_wait.parity.acquire.cta.shared::cta.b64 P, [%0], %1, 0x989680;\n\t"
        "@P bra.uni WAITDONE_%=;\n\t"
        "bra.uni WAITLOOP_%=;\n\t"
        "WAITDONE_%=:\n\t"
        "}" :: "r"(mbar), "r"(parity) : "memory");
}
__device__ __forceinline__ void bulk_cp(uint32_t dst, const void* src,
                                        uint32_t bytes, uint32_t mbar) {
    asm volatile(
        "cp.async.bulk.shared::cluster.global.mbarrier::complete_tx::bytes "
        "[%0], [%1], %2, [%3];"
        :: "r"(dst), "l"(src), "r"(bytes), "r"(mbar) : "memory");
}

// ---------------- Kernel 1: ONE-launch prep (pre-swizzled blobs) -----------
// blocks [0,512):    B blobs = fp16(sn_norm / 8); blocks [0,64) zero output.
// blocks [512,4608): one (b, c, 128-w tile): window inv-norms from a
//                    192-float x slice, then A blob = fp16(x_window * inv).
__global__ __launch_bounds__(256) void prep_kernel(const float* __restrict__ x,
                                                   const float* __restrict__ sh,
                                                   float* __restrict__ out) {
    __shared__ float xs[192];
    __shared__ float invs[128];
    const int tid = threadIdx.x;
    if (blockIdx.x < 512) {
        if (blockIdx.x < 64) out[blockIdx.x * 256 + tid] = 0.f;
        int gw   = (blockIdx.x * 256 + tid) >> 5;
        int lane = tid & 31;
        int c = gw / NK, k = gw % NK;
        const float* row = sh + (size_t)(c * NK + k) * NS;
        float v0 = row[lane], v1 = row[lane + 32];
        float ss = v0 * v0 + v1 * v1;
        #pragma unroll
        for (int o = 16; o > 0; o >>= 1) ss += __shfl_xor_sync(0xffffffffu, ss, o);
        float sc = 0.125f / fmaxf(sqrtf(ss), 1e-8f);
        // B blob layout: ntile = k>>7, row r = k&127, chunk = c
        char* blob = (char*)g_Bsw + ((((size_t)(k >> 7)) * 8 + c) << 14);
        int r = k & 127;
        #pragma unroll
        for (int h = 0; h < 2; ++h) {
            int s = lane + 32 * h;
            int c16 = s >> 3, inner = s & 7;
            uint32_t off = (uint32_t)(r * 128 + ((c16 ^ (r & 7)) << 4) + inner * 2);
            *reinterpret_cast<__half*>(blob + off) = __float2half(h ? v1 * sc : v0 * sc);
        }
        return;
    }
    const int id = blockIdx.x - 512;       // 0..4095
    const int wt = id & 15;
    const int c  = (id >> 4) & 7;
    const int b  = id >> 7;
    const int w0 = wt * 128;

    if (tid < 192) {
        int j = w0 + tid;
        xs[tid] = (j < NL) ? x[((size_t)(b * NC + c)) * NL + j] : 0.f;
    }
    __syncthreads();
    if (tid < 128) {
        int w = w0 + tid;
        if (w < NW) {
            float ss = 0.f;
            #pragma unroll 16
            for (int s = 0; s < NS; ++s) { float v = xs[tid + s]; ss += v * v; }
            invs[tid] = 1.0f / fmaxf(sqrtf(ss), 1e-8f);
        } else {
            invs[tid] = 0.f;
        }
    }
    __syncthreads();
    char* blob = (char*)g_Asw + ((((size_t)(b * 16 + wt)) * 8 + c) << 14);
    #pragma unroll
    for (int it = 0; it < 4; ++it) {
        int idx = it * 256 + tid;           // 1024 16B-chunks: 128 rows x 8
        int r = idx >> 3, c16 = idx & 7;
        float inv = invs[r];
        __half h[8];
        #pragma unroll
        for (int j = 0; j < 8; ++j) h[j] = __float2half(xs[r + c16 * 8 + j] * inv);
        uint32_t so = (uint32_t)(r * 128 + ((c16 ^ (r & 7)) << 4));
        *reinterpret_cast<uint4*>(blob + so) = *reinterpret_cast<uint4*>(h);
    }
}

// ---------------- Kernel 2: async-pipelined fp32-acc mma GEMM --------------
// Block tile M=128 x N=128, 128 threads (4 warps, 2x2), warp tile 64x64.
// 2 CTAs/SM. 8 K-chunks, 3 stages; cp.async.bulk blob copies signalled by
// mbarrier complete_tx. No __syncthreads in the mainloop. Fragments are
// software-pipelined ACROSS chunk boundaries: at ks==3 the next chunk's
// full-wait + ks=0 ldsm overlap the last 32 MMAs of the current chunk.
#define NSTAGE 3
#define STAGE_BYTES 32768
#define OFF_B 16384
#define MBAR_OFF (NSTAGE * STAGE_BYTES)          // 98304
#define SMEM_BYTES (MBAR_OFF + 64)               // 98368 per CTA

__global__ __launch_bounds__(128, 2) void gemm_kernel(float* __restrict__ out) {
    extern __shared__ char smem[];
    const uint32_t sb = smem_u32(smem);
    const int tid = threadIdx.x;
    const int wid = tid >> 5, lane = tid & 31;
    const int n0 = blockIdx.y * 128, b = blockIdx.z;

    const int wm = wid & 1, wn = wid >> 1;   // 2 x 2 warp grid

    const int t8 = lane >> 3, lr = lane & 7;
    const int arow = wm * 64 + (t8 & 1) * 8 + lr;   // + i*16, i<4
    const int achk = t8 >> 1;                        // + 2*ks
    const int brow = wn * 64 + (t8 >> 1) * 8 + lr;  // + p*16, p<4
    const int bchk = t8 & 1;                         // + 2*ks
    const int arow7 = arow & 7, brow7 = brow & 7;
    const uint32_t aRowB0 = (uint32_t)(arow * 128);
    const uint32_t bRowB0 = (uint32_t)(brow * 128);

    const char* Ablob0 = (const char*)g_Asw +
                         (((size_t)(b * 16 + blockIdx.x)) * 8 << 14);
    const char* Bblob0 = (const char*)g_Bsw + ((size_t)blockIdx.y * 8 << 14);

    const uint32_t mb_full0  = sb + MBAR_OFF;        // +8 per slot
    const uint32_t mb_empty0 = sb + MBAR_OFF + 24;   // +8 per slot

    if (tid == 0) {
        #pragma unroll
        for (int s = 0; s < NSTAGE; ++s) {
            mbar_init(mb_full0 + s * 8, 1);    // tx-based completion
            mbar_init(mb_empty0 + s * 8, 4);   // one arrive per warp
        }
    }
    __syncthreads();

    // producer cursor (tid 0 only): phase starts 1 so first waits pass
    int prod_slot = 0, prod_ph = 1;
    auto issue = [&](int cc) {
        const uint32_t fullb = mb_full0 + prod_slot * 8;
        mbar_wait(mb_empty0 + prod_slot * 8, (uint32_t)prod_ph);
        mbar_expect_tx(fullb, 2 * 16384u);
        const uint32_t dst = sb + prod_slot * STAGE_BYTES;
        bulk_cp(dst,         Ablob0 + ((size_t)cc << 14), 16384u, fullb);
        bulk_cp(dst + OFF_B, Bblob0 + ((size_t)cc << 14), 16384u, fullb);
        if (++prod_slot == NSTAGE) { prod_slot = 0; prod_ph ^= 1; }
    };

    uint32_t ah[2][4][4], bh[2][4][4];   // double-buffered fragments
    auto ldfrags = [&](uint32_t base, int ks, int v) {
        const uint32_t aH = base, bH = base + OFF_B;
        const uint32_t axo = (uint32_t)(((achk + 2 * ks) ^ arow7) << 4);
        #pragma unroll
        for (int i = 0; i < 4; ++i)
            ldsm4(ah[v][i], aH + aRowB0 + (uint32_t)(i * 16 * 128) + axo);
        const uint32_t bxo = (uint32_t)(((bchk + 2 * ks) ^ brow7) << 4);
        #pragma unroll
        for (int p = 0; p < 4; ++p)
            ldsm4(bh[v][p], bH + bRowB0 + (uint32_t)(p * 16 * 128) + bxo);
    };

    float acc[4][8][4];
    #pragma unroll
    for (int i = 0; i < 4; ++i)
        #pragma unroll
        for (int j = 0; j < 8; ++j)
            #pragma unroll
            for (int c = 0; c < 4; ++c) acc[i][j][c] = 0.f;

    if (tid == 0) { issue(0); issue(1); }

    // consumer cursor: phase starts 0. Preload chunk 0 ks=0 fragments.
    int cons_slot = 0, cons_ph = 0;
    mbar_wait(mb_full0, 0u);
    ldfrags(sb, 0, 0);

    for (int cc = 0; cc < 8; ++cc) {
        if (tid == 0 && cc < 6) issue(cc + 2);

        const uint32_t cbase = sb + cons_slot * STAGE_BYTES;
        const int nslot = (cons_slot + 1 == NSTAGE) ? 0 : cons_slot + 1;
        const int nph   = (cons_slot + 1 == NSTAGE) ? (cons_ph ^ 1) : cons_ph;

        #pragma unroll
        for (int ks = 0; ks < 4; ++ks) {
            const int cur = ks & 1;
            if (ks < 3) {
                ldfrags(cbase, ks + 1, cur ^ 1);
                // last read of this stage happens at ks==2 (loads ks=3 frags)
                if (ks == 2 && lane == 0) mbar_arrive(mb_empty0 + cons_slot * 8);
            } else if (cc < 7) {
                // overlap next chunk's wait + ks=0 ldsm with final MMAs
                mbar_wait(mb_full0 + nslot * 8, (uint32_t)nph);
                ldfrags(sb + nslot * STAGE_BYTES, 0, cur ^ 1);
            }
            #pragma unroll
            for (int p = 0; p < 4; ++p) {
                #pragma unroll
                for (int i = 0; i < 4; ++i) {
                    mma16816(acc[i][2 * p],     ah[cur][i], &bh[cur][p][0]);
                    mma16816(acc[i][2 * p + 1], ah[cur][i], &bh[cur][p][2]);
                }
            }
        }
        cons_slot = nslot; cons_ph = nph;
    }
    __syncthreads();   // all copies consumed; safe to reuse smem

    // ---------------- epilogue: max over M (relu via 0-init) ---------------
    int* s_max = reinterpret_cast<int*>(smem);
    s_max[tid] = 0;
    __syncthreads();

    #pragma unroll
    for (int j = 0; j < 8; ++j) {
        float v0 = fmaxf(fmaxf(acc[0][j][0], acc[0][j][2]),
                         fmaxf(acc[1][j][0], acc[1][j][2]));
        v0 = fmaxf(v0, fmaxf(fmaxf(acc[2][j][0], acc[2][j][2]),
                             fmaxf(acc[3][j][0], acc[3][j][2])));
        float v1 = fmaxf(fmaxf(acc[0][j][1], acc[0][j][3]),
                         fmaxf(acc[1][j][1], acc[1][j][3]));
        v1 = fmaxf(v1, fmaxf(fmaxf(acc[2][j][1], acc[2][j][3]),
                             fmaxf(acc[3][j][1], acc[3][j][3])));
        #pragma unroll
        for (int off = 4; off < 32; off <<= 1) {
            v0 = fmaxf(v0, __shfl_xor_sync(0xffffffffu, v0, off));
            v1 = fmaxf(v1, __shfl_xor_sync(0xffffffffu, v1, off));
        }
        if (lane < 4) {
            int col = wn * 64 + j * 8 + lane * 2;
            atomicMax(&s_max[col],     __float_as_int(v0));
            atomicMax(&s_max[col + 1], __float_as_int(v1));
        }
    }
    __syncthreads();

    // all candidates >= 0 vs 0-init: signed-int max == relu'd float max
    atomicMax(reinterpret_cast<int*>(out + (size_t)b * NK + n0 + tid), s_max[tid]);
}

// ---------------- launch -----------------------------------------------------
extern "C" void kernel_launch(void* const* d_in, const int* in_sizes, int n_in,
                              void* d_out, int out_size) {
    const float* x  = (const float*)d_in[0];   // (B, C, L)
    const float* sh = (const float*)d_in[1];   // (C, K, S)
    float* out = (float*)d_out;                // (B, 1, K)

    prep_kernel<<<4608, 256>>>(x, sh, out);

    cudaFuncSetAttribute(gemm_kernel, cudaFuncAttributeMaxDynamicSharedMemorySize,
                         SMEM_BYTES);
    gemm_kernel<<<dim3(16, 4, 32), 128, SMEM_BYTES>>>(out);
}